// round 16
// baseline (speedup 1.0000x reference)
#include <cuda_runtime.h>
#include <math_constants.h>

#define NB 50
#define S51 51
#define BATCH 4096
#define NFEAT 100
#define ALPHA_INV (1.0f/0.9f)

#define TPB  256             // 8 warps = 4 quarters x 2 warps (64 threads)
#define QCOL 64              // eval columns per block; 4 evals each -> 256 evals

// ---------------- device globals (scratch) ----------------------------------
__device__ float g_xm[BATCH];
__device__ float g_x[BATCH];
__device__ float g_x2[BATCH];
__device__ float g_xfinal;
__device__ float g_ccw[S51];
__device__ float g_ccs[S51];
__device__ float g_vals[2][BATCH * 52];

// ---------------- packed f32x2 helpers --------------------------------------
__device__ __forceinline__ unsigned long long fma2(unsigned long long a,
                                                   unsigned long long b,
                                                   unsigned long long c) {
    unsigned long long d;
    asm("fma.rn.f32x2 %0, %1, %2, %3;" : "=l"(d) : "l"(a), "l"(b), "l"(c));
    return d;
}
__device__ __forceinline__ unsigned long long pack2(float lo, float hi) {
    unsigned long long d;
    asm("mov.b64 %0, {%1, %2};" : "=l"(d) : "f"(lo), "f"(hi));
    return d;
}
__device__ __forceinline__ void unpack2(unsigned long long v, float& lo, float& hi) {
    asm("mov.b64 {%0, %1}, %2;" : "=f"(lo), "=f"(hi) : "l"(v));
}

// ---------------- SMEM layout (floats), dynamic --------------------------------
// Act buffer: [65 rows][64 cols x 4 evals] floats; row 64 = prefetch pad.
#define ACT_ROW 256
#define OFF_ACT   0            // 65*256 = 16640
#define OFF_W1T   16640        // transposed W1 [k][j]
#define OFF_W2T   20736
#define OFF_W0    24832        // [64][8]
#define OFF_B1    25344
#define OFF_B2    25408
#define OFF_W3    25472        // 64
#define OFF_WF    25536        // 5
#define OFF_B3    25541
#define OFF_PART  25544        // layer-3 partials: 4 quarters x 64 cols x 4 = 1024
#define SMEM_FLOATS 26568
#define SMEM_BYTES (SMEM_FLOATS * 4)   // 106272 B -> 2 blocks = 212.5KB <= 228KB

// ---------------- CC weights (fp64, parallel) ---------------------------------
__global__ void k_init_cc() {
    __shared__ double sred[64];
    int j = blockIdx.x, i = threadIdx.x;
    double t = 0.0;
    if (i <= NB) {
        double w;
        if (i & 1)        w = 0.0;
        else if (i == 0)  w = 1.0;
        else              w = 2.0 / (1.0 - (double)i * (double)i);
        double l;
        if (j == 0) l = 0.5;
        else {
            l = cos((double)i * (double)j * CUDART_PI / (double)NB);
            if (j == NB) l *= 0.5;
        }
        t = l * (2.0 / (double)NB) * w;
    }
    sred[i] = t;
    __syncthreads();
    for (int off = 32; off; off >>= 1) {
        if (i < off) sred[i] += sred[i + off];
        __syncthreads();
    }
    if (i == 0) {
        g_ccw[j] = (float)sred[0];
        g_ccs[j] = (float)cos((double)j * CUDART_PI / (double)NB);
    }
}

// ---------------- xm = x_ @ log_weight ----------------------------------------
__global__ void k_xm(const float* __restrict__ x_, const float* __restrict__ lw) {
    int warp = (blockIdx.x * blockDim.x + threadIdx.x) >> 5;
    int lane = threadIdx.x & 31;
    if (warp >= BATCH) return;
    const float* row = x_ + (size_t)warp * NFEAT;
    float p = 0.f;
    for (int j = lane; j < NFEAT; j += 32) p = fmaf(row[j], lw[j], p);
    #pragma unroll
    for (int off = 16; off; off >>= 1) p += __shfl_xor_sync(0xffffffffu, p, off);
    if (lane == 0) g_xm[warp] = p;
}

// ---------------- per-step prep ------------------------------------------------
__global__ void k_prep(const float* __restrict__ sp, const float* __restrict__ out, int step) {
    __shared__ float smax[1024];
    int tid = threadIdx.x;
    float lam = 1.f / (1.f + __expf(-sp[0]));
    float lmax = -CUDART_INF_F;
    for (int b = tid; b < BATCH; b += 1024) {
        float I1v = step ? out[b]             : 0.f;
        float I2v = step ? out[2 * BATCH + b] : 0.f;
        float xmv = g_xm[b];
        g_x[b]  = (1.f - lam) * xmv + lam * I1v;
        float x2v = (1.f - lam) * xmv + lam * I2v;
        g_x2[b] = x2v;
        lmax = fmaxf(lmax, x2v);
    }
    smax[tid] = lmax;
    __syncthreads();
    for (int off = 512; off; off >>= 1) {
        if (tid < off) smax[tid] = fmaxf(smax[tid], smax[tid + off]);
        __syncthreads();
    }
    if (tid == 0) g_xfinal = smax[0] + 10.f;
}

// ---------------- 64->64 quarter-layer: thread = 4 evals x 16 neurons ----------
__device__ __forceinline__ void layer_q(const float* __restrict__ sWT,
                                        const float* __restrict__ sbias,
                                        const float* __restrict__ actCol, int qh,
                                        unsigned long long acc[4][8]) {
    #pragma unroll
    for (int jp = 0; jp < 8; ++jp) {
        unsigned long long bp = *(const unsigned long long*)(sbias + qh * 16 + 2 * jp);
        acc[0][jp] = bp; acc[1][jp] = bp; acc[2][jp] = bp; acc[3][jp] = bp;
    }

    float4 apn = *(const float4*)(actCol);    // k=0

    #pragma unroll 2
    for (int k = 0; k < 64; ++k) {
        unsigned long long a2x = pack2(apn.x, apn.x);
        unsigned long long a2y = pack2(apn.y, apn.y);
        unsigned long long a2z = pack2(apn.z, apn.z);
        unsigned long long a2w = pack2(apn.w, apn.w);
        apn = *(const float4*)(actCol + (k + 1) * ACT_ROW);   // row 64 = pad

        const ulonglong2* w4 = (const ulonglong2*)(sWT + k * 64 + qh * 16);
        #pragma unroll
        for (int i = 0; i < 4; ++i) {
            ulonglong2 wv = w4[i];                 // warp-uniform broadcast LDS.128
            acc[0][2 * i]     = fma2(wv.x, a2x, acc[0][2 * i]);
            acc[0][2 * i + 1] = fma2(wv.y, a2x, acc[0][2 * i + 1]);
            acc[1][2 * i]     = fma2(wv.x, a2y, acc[1][2 * i]);
            acc[1][2 * i + 1] = fma2(wv.y, a2y, acc[1][2 * i + 1]);
            acc[2][2 * i]     = fma2(wv.x, a2z, acc[2][2 * i]);
            acc[2][2 * i + 1] = fma2(wv.y, a2z, acc[2][2 * i + 1]);
            acc[3][2 * i]     = fma2(wv.x, a2w, acc[3][2 * i]);
            acc[3][2 * i + 1] = fma2(wv.y, a2w, acc[3][2 * i + 1]);
        }
    }
}

// ReLU + transpose (eval-major acc -> row-major float4) + store own 16 rows.
__device__ __forceinline__ void store_q(float* __restrict__ actCol, int qh,
                                        unsigned long long acc[4][8]) {
    #pragma unroll
    for (int jp = 0; jp < 8; ++jp) {
        float lo0, hi0, lo1, hi1, lo2, hi2, lo3, hi3;
        unpack2(acc[0][jp], lo0, hi0);
        unpack2(acc[1][jp], lo1, hi1);
        unpack2(acc[2][jp], lo2, hi2);
        unpack2(acc[3][jp], lo3, hi3);
        float4 vl = make_float4(fmaxf(lo0, 0.f), fmaxf(lo1, 0.f),
                                fmaxf(lo2, 0.f), fmaxf(lo3, 0.f));
        float4 vh = make_float4(fmaxf(hi0, 0.f), fmaxf(hi1, 0.f),
                                fmaxf(hi2, 0.f), fmaxf(hi3, 0.f));
        *(float4*)(actCol + (qh * 16 + 2 * jp) * ACT_ROW)     = vl;
        *(float4*)(actCol + (qh * 16 + 2 * jp + 1) * ACT_ROW) = vh;
    }
}

// ---------------- eval kernel ----------------------------------------------------
template <int MODE>
__global__ void __launch_bounds__(TPB, 2) k_eval(
    const float* __restrict__ W0, const float* __restrict__ b0,
    const float* __restrict__ W1, const float* __restrict__ b1,
    const float* __restrict__ W2, const float* __restrict__ b2,
    const float* __restrict__ W3, const float* __restrict__ b3,
    const float* __restrict__ Wf, const float* __restrict__ h,
    float* __restrict__ out)
{
    extern __shared__ float sm[];
    const int tid = threadIdx.x;
    const int qh  = tid / QCOL;        // neuron quarter (2-warp granularity)
    const int col = tid - qh * QCOL;   // eval column

    // ---- cooperative fill ----
    for (int idx = tid; idx < 4096; idx += TPB) {
        int k = idx >> 6, j = idx & 63;
        sm[OFF_W1T + idx] = W1[j * 64 + k];
        sm[OFF_W2T + idx] = W2[j * 64 + k];
    }
    if (tid < 64) {
        #pragma unroll
        for (int d = 0; d < 5; ++d) sm[OFF_W0 + tid * 8 + d] = W0[tid * 5 + d];
        sm[OFF_W0 + tid * 8 + 5] = b0[tid];
        sm[OFF_B1 + tid] = b1[tid];
        sm[OFF_B2 + tid] = b2[tid];
        sm[OFF_W3 + tid] = W3[tid];
    }
    if (tid < 5)   sm[OFF_WF + tid] = Wf[tid];
    if (tid == 64) sm[OFF_B3] = b3[0];

    // ---- per-eval params: 4 consecutive evals per column ----
    constexpr int NS  = (MODE == 0) ? 52 : 51;
    constexpr int TOT = BATCH * NS;
    const int Ebase = (blockIdx.x * QCOL + col) * 4;

    float  X[4];
    int    row[4], slot[4];
    bool   valid[4];
    float4 hv[4];
    #pragma unroll
    for (int e = 0; e < 4; ++e) {
        int E = Ebase + e;
        valid[e] = (E < TOT);
        if (!valid[e]) E = 0;
        row[e]  = E / NS;
        slot[e] = E - row[e] * NS;
        float lo = (MODE == 0) ? 0.f : g_x2[row[e]];
        float hi = (MODE == 0) ? g_x[row[e]] : g_xfinal;
        int sc = (slot[e] < S51) ? slot[e] : 0;
        X[e] = lo + (hi - lo) * (g_ccs[sc] + 1.f) * 0.5f;
        if (MODE == 0 && slot[e] == S51) X[e] = g_x2[row[e]];
        hv[e] = ((const float4*)h)[row[e]];
    }

    __syncthreads();

    float* actCol = sm + OFF_ACT + 4 * col;

    // ---- layer 0: own 16 neurons for 4 evals ----
    #pragma unroll 4
    for (int j = 0; j < 16; ++j) {
        const float* w = sm + OFF_W0 + (qh * 16 + j) * 8;   // broadcast
        float w0 = w[0], w1 = w[1], w2 = w[2], w3v = w[3], w4 = w[4], bb = w[5];
        float4 v;
        v.x = fmaf(w0, X[0], bb); v.y = fmaf(w0, X[1], bb);
        v.z = fmaf(w0, X[2], bb); v.w = fmaf(w0, X[3], bb);
        v.x = fmaf(w1, hv[0].x, v.x); v.y = fmaf(w1, hv[1].x, v.y);
        v.z = fmaf(w1, hv[2].x, v.z); v.w = fmaf(w1, hv[3].x, v.w);
        v.x = fmaf(w2, hv[0].y, v.x); v.y = fmaf(w2, hv[1].y, v.y);
        v.z = fmaf(w2, hv[2].y, v.z); v.w = fmaf(w2, hv[3].y, v.w);
        v.x = fmaf(w3v, hv[0].z, v.x); v.y = fmaf(w3v, hv[1].z, v.y);
        v.z = fmaf(w3v, hv[2].z, v.z); v.w = fmaf(w3v, hv[3].z, v.w);
        v.x = fmaf(w4, hv[0].w, v.x); v.y = fmaf(w4, hv[1].w, v.y);
        v.z = fmaf(w4, hv[2].w, v.z); v.w = fmaf(w4, hv[3].w, v.w);
        v.x = fmaxf(v.x, 0.f); v.y = fmaxf(v.y, 0.f);
        v.z = fmaxf(v.z, 0.f); v.w = fmaxf(v.w, 0.f);
        *(float4*)(actCol + (qh * 16 + j) * ACT_ROW) = v;
    }
    __syncthreads();

    unsigned long long acc[4][8];

    // ---- layer 1 ----
    layer_q(sm + OFF_W1T, sm + OFF_B1, actCol, qh, acc);
    __syncthreads();                            // all reads done before overwrite
    store_q(actCol, qh, acc);
    __syncthreads();

    // ---- layer 2 ----
    layer_q(sm + OFF_W2T, sm + OFF_B2, actCol, qh, acc);
    __syncthreads();
    store_q(actCol, qh, acc);
    __syncthreads();

    // ---- layer 3: partial dot over own 16 rows ----
    float y0 = 0.f, y1 = 0.f, y2 = 0.f, y3 = 0.f;
    #pragma unroll
    for (int kk = 0; kk < 16; ++kk) {
        float4 ap = *(const float4*)(actCol + (qh * 16 + kk) * ACT_ROW);
        float w = sm[OFF_W3 + qh * 16 + kk];
        y0 = fmaf(w, ap.x, y0); y1 = fmaf(w, ap.y, y1);
        y2 = fmaf(w, ap.z, y2); y3 = fmaf(w, ap.w, y3);
    }
    *(float4*)(sm + OFF_PART + (qh * QCOL + col) * 4) = make_float4(y0, y1, y2, y3);
    __syncthreads();

    if (qh == 0) {
        float4 p1 = *(const float4*)(sm + OFF_PART + (QCOL + col) * 4);
        float4 p2 = *(const float4*)(sm + OFF_PART + (2 * QCOL + col) * 4);
        float4 p3 = *(const float4*)(sm + OFF_PART + (3 * QCOL + col) * 4);
        float b3v = sm[OFF_B3];
        float y[4];
        y[0] = y0 + p1.x + p2.x + p3.x + b3v;
        y[1] = y1 + p1.y + p2.y + p3.y + b3v;
        y[2] = y2 + p1.z + p2.z + p3.z + b3v;
        y[3] = y3 + p1.w + p2.w + p3.w + b3v;

        constexpr float P0 = (MODE == 0) ? 1.1f : 1.5f;
        constexpr float P1 = (MODE == 0) ? 1.1f : 2.0f;
        constexpr float P2 = (MODE == 0) ? 1.5f : 2.5f;
        constexpr float P3 = (MODE == 0) ? 2.0f : 3.0f;
        constexpr float P4 = (MODE == 0) ? 2.5f : 3.5f;
        const float wf0 = sm[OFF_WF + 0], wf1 = sm[OFF_WF + 1], wf2 = sm[OFF_WF + 2];
        const float wf3 = sm[OFF_WF + 3], wf4 = sm[OFF_WF + 4];

        #pragma unroll
        for (int e = 0; e < 4; ++e) {
            float z  = (y[e] > 0.f) ? (y[e] + 1.f) : __expf(y[e]);
            float lg = __log2f(z);
            float g = 0.f;
            g += __fdividef(wf0, exp2f(P0 * lg) + 1.f);
            g += __fdividef(wf1, exp2f(P1 * lg) + 1.f);
            g += __fdividef(wf2, exp2f(P2 * lg) + 1.f);
            g += __fdividef(wf3, exp2f(P3 * lg) + 1.f);
            g += __fdividef(wf4, exp2f(P4 * lg) + 1.f);
            float val = fmaxf(g, 0.f);

            if (valid[e]) {
                if (MODE == 0 && slot[e] == S51) out[BATCH + row[e]] = val;   // out_first
                else g_vals[MODE][row[e] * 52 + slot[e]] = g_ccw[slot[e]] * val;
            }
        }
    }
}

// ---------------- merged deterministic quadrature reduce -----------------------
__global__ void k_reduce(float* __restrict__ out) {
    const bool m0 = (blockIdx.x < BATCH / 8);
    int blk  = m0 ? blockIdx.x : blockIdx.x - BATCH / 8;
    int row  = blk * 8 + (threadIdx.x >> 5);
    int lane = threadIdx.x & 31;
    const float* v = (m0 ? g_vals[0] : g_vals[1]) + row * 52;
    float s = v[lane];
    if (lane < 19) s += v[32 + lane];
    #pragma unroll
    for (int off = 16; off; off >>= 1) s += __shfl_xor_sync(0xffffffffu, s, off);
    if (lane == 0) {
        if (m0) out[row]             = s * g_x[row] * 0.5f;
        else    out[2 * BATCH + row] = s * (g_xfinal - g_x2[row]) * 0.5f * ALPHA_INV;
    }
}

// ---------------- launch ---------------------------------------------------------
extern "C" void kernel_launch(void* const* d_in, const int* in_sizes, int n_in,
                              void* d_out, int out_size) {
    (void)in_sizes; (void)n_in; (void)out_size;
    const float* x_ = (const float*)d_in[0];
    const float* h_ = (const float*)d_in[1];
    const float* lw = (const float*)d_in[2];
    const float* sp = (const float*)d_in[3];
    const float* f1p[9] = { (const float*)d_in[4],  (const float*)d_in[5],
                            (const float*)d_in[6],  (const float*)d_in[7],
                            (const float*)d_in[8],  (const float*)d_in[9],
                            (const float*)d_in[10], (const float*)d_in[11],
                            (const float*)d_in[12] };
    const float* f2p[9] = { (const float*)d_in[13], (const float*)d_in[14],
                            (const float*)d_in[15], (const float*)d_in[16],
                            (const float*)d_in[17], (const float*)d_in[18],
                            (const float*)d_in[19], (const float*)d_in[20],
                            (const float*)d_in[21] };
    float* out = (float*)d_out;

    cudaFuncSetAttribute(k_eval<0>, cudaFuncAttributeMaxDynamicSharedMemorySize, SMEM_BYTES);
    cudaFuncSetAttribute(k_eval<1>, cudaFuncAttributeMaxDynamicSharedMemorySize, SMEM_BYTES);

    k_init_cc<<<S51, 64>>>();
    k_xm<<<BATCH / 8, 256>>>(x_, lw);

    for (int step = 0; step < 2; ++step) {
        k_prep<<<1, 1024>>>(sp, out, step);
        // MODE 0: 212992 evals / 256 per block -> 832 blocks (exact)
        k_eval<0><<<832, TPB, SMEM_BYTES>>>(f1p[0], f1p[1], f1p[2], f1p[3], f1p[4],
                                            f1p[5], f1p[6], f1p[7], f1p[8], h_, out);
        // MODE 1: 208896 evals / 256 per block -> 816 blocks (exact)
        k_eval<1><<<816, TPB, SMEM_BYTES>>>(f2p[0], f2p[1], f2p[2], f2p[3], f2p[4],
                                            f2p[5], f2p[6], f2p[7], f2p[8], h_, out);
        k_reduce<<<2 * (BATCH / 8), 256>>>(out);
    }
}